// round 4
// baseline (speedup 1.0000x reference)
#include <cuda_runtime.h>
#include <cstdint>
#include <cmath>

typedef unsigned long long u64;

#define NT 448                  // 14 warps per CTA, 1 CTA/SM, grid=147
#define HNT 224                 // threads per muscle-half; pairs per CTA
#define PM 2344                 // floats per muscle block in smem
#define OFF_W1T 0               // 3*32 transposed [i][o]
#define OFF_B1P 96              // 32
#define OFF_W2  128             // 32*32 NATIVE [o][i]
#define OFF_B2Z 1152            // 64  ({b_o, 0} interleaved)
#define OFF_W3  1216            // 32*32 NATIVE [o][i]
#define OFF_B3Z 2240            // 64
#define OFF_W4  2304            // 32 native [i]
#define OFF_B4  2336            // 1
#define OFF_PAR 2337            // 7: K0,K1,L0,L1,Ms,Ms2,K1L1
#define OFF_RED (8*PM)          // reduction buffer: HNT float4
#define SMEM_BYTES ((8*PM + HNT*4)*4)
#define DTC 0.0166667f
#define NNR 0.3f

// ---------- packed f32x2 helpers ----------
__device__ __forceinline__ u64 fma2(u64 a, u64 b, u64 c) {
    u64 d; asm("fma.rn.f32x2 %0, %1, %2, %3;" : "=l"(d) : "l"(a), "l"(b), "l"(c)); return d;
}
__device__ __forceinline__ u64 add2(u64 a, u64 b) {
    u64 d; asm("add.rn.f32x2 %0, %1, %2;" : "=l"(d) : "l"(a), "l"(b)); return d;
}
__device__ __forceinline__ u64 mul2(u64 a, u64 b) {
    u64 d; asm("mul.rn.f32x2 %0, %1, %2;" : "=l"(d) : "l"(a), "l"(b)); return d;
}
__device__ __forceinline__ u64 pack2(float lo, float hi) {
    u64 r; asm("mov.b64 %0, {%1, %2};" : "=l"(r) : "r"(__float_as_uint(lo)), "r"(__float_as_uint(hi))); return r;
}
__device__ __forceinline__ void unpack2(u64 v, float& lo, float& hi) {
    unsigned a, b; asm("mov.b64 {%0, %1}, %2;" : "=r"(a), "=r"(b) : "l"(v));
    lo = __uint_as_float(a); hi = __uint_as_float(b);
}
__device__ __forceinline__ float tanh_ap(float x) {
    float y; asm("tanh.approx.f32 %0, %1;" : "=f"(y) : "f"(x)); return y;
}
__device__ __forceinline__ u64 leaky2(u64 x, u64 c505, u64 c495) {
    u64 ax = x & 0x7FFFFFFF7FFFFFFFull;
    return fma2(x, c505, mul2(ax, c495));
}
__device__ __forceinline__ float leakys(float x) {
    return fmaf(0.505f, x, 0.495f * fabsf(x));
}

// closed-form 2x2 expm + phi1 solve (validated: rel_err 5.7e-7)
__device__ __forceinline__ void finalize(float Ks, float Bs, float s0, float s1,
                                         float Iv, float invI, float Bv, float Kv,
                                         float& o0, float& o1) {
    float A10 = -(Ks + Kv) * invI;
    float Dd  = 2.0f * sqrtf(fmaxf(Ks * Iv, 0.0f));
    float A11 = -(Dd + Bv) * invI;
    float B10 = Bs * invI;
    float a10 = A10 * DTC, a11 = A11 * DTC;
    float s = 0.5f * a11;
    float q = fmaf(s, s, DTC * a10);
    float c, kf;
    if (q >= 0.0f) {
        float w = sqrtf(q);
        c = coshf(w);
        kf = (w > 1e-4f) ? sinhf(w) / w : 1.0f + q * (1.0f / 6.0f);
    } else {
        float w = sqrtf(-q);
        c = __cosf(w);
        kf = (w > 1e-4f) ? __sinf(w) / w : 1.0f + q * (1.0f / 6.0f);
    }
    float es = __expf(s);
    float g  = es * fmaf(-s, kf, c);
    float kk = es * kf;
    float Ad01 = kk * DTC;
    float Ad10 = kk * a10;
    float Ad11 = g + kk * a11;
    float v  = DTC * B10;
    float y1 = kk * v;
    float r1 = (Ad11 - 1.0f) * v;
    float y0 = (r1 - a11 * y1) / a10;
    o0 = fmaf(g,    s0, fmaf(Ad01, s1, y0));
    o1 = fmaf(Ad10, s0, fmaf(Ad11, s1, y1));
}

__global__ __launch_bounds__(NT, 1)
void joint_kernel(const float* __restrict__ SS,  const float* __restrict__ AL,
                  const float* __restrict__ K0,  const float* __restrict__ K1,
                  const float* __restrict__ L0,  const float* __restrict__ L1,
                  const float* __restrict__ Ms,  const float* __restrict__ Ip,
                  const float* __restrict__ Bvp, const float* __restrict__ Kvp,
                  const float* __restrict__ W1,  const float* __restrict__ b1,
                  const float* __restrict__ W2,  const float* __restrict__ b2,
                  const float* __restrict__ W3,  const float* __restrict__ b3,
                  const float* __restrict__ W4,  const float* __restrict__ b4,
                  float* __restrict__ out, int B) {
    extern __shared__ float sm[];
    const int tid = threadIdx.x;

    // ---- smem tables ----
    for (int t = tid; t < 768; t += NT) {            // W1[m][o][i] -> [m][i][o]
        int m = t / 96, r = t - m * 96, o = r / 3, i = r - o * 3;
        sm[m * PM + OFF_W1T + i * 32 + o] = W1[t];
    }
    for (int t = tid; t < 256; t += NT) {            // b1 native
        int m = t >> 5, o = t & 31;
        sm[m * PM + OFF_B1P + o] = b1[t];
    }
    {                                                // W2, W3 native copies (float4)
        const float4* s2 = reinterpret_cast<const float4*>(W2);
        const float4* s3 = reinterpret_cast<const float4*>(W3);
        for (int t = tid; t < 2048; t += NT) {
            int m = t >> 8, r = t & 255;
            *reinterpret_cast<float4*>(&sm[m * PM + OFF_W2 + r * 4]) = s2[t];
            *reinterpret_cast<float4*>(&sm[m * PM + OFF_W3 + r * 4]) = s3[t];
        }
    }
    for (int t = tid; t < 512; t += NT) {            // b2, b3 as {b, 0}
        int m = t >> 6, r = t & 63;
        float v2 = (r & 1) ? 0.0f : b2[m * 32 + (r >> 1)];
        float v3 = (r & 1) ? 0.0f : b3[m * 32 + (r >> 1)];
        sm[m * PM + OFF_B2Z + r] = v2;
        sm[m * PM + OFF_B3Z + r] = v3;
    }
    for (int t = tid; t < 256; t += NT) {            // W4 native
        int m = t >> 5, i = t & 31;
        sm[m * PM + OFF_W4 + i] = W4[t];
    }
    if (tid < 8) {
        int m = tid;
        sm[m * PM + OFF_B4] = b4[m];
        float k0 = K0[m], k1 = K1[m], l0 = L0[m], l1 = L1[m], ms = Ms[m];
        float* p = sm + m * PM + OFF_PAR;
        p[0] = k0; p[1] = k1; p[2] = l0; p[3] = l1;
        p[4] = ms; p[5] = ms * ms; p[6] = k1 * l1;
    }
    __syncthreads();

    // thread -> (pair, muscle half)
    const int lane  = tid % HNT;          // pair slot within CTA
    const int half  = tid / HNT;          // 0: muscles 0-3, 1: muscles 4-7
    const int pairs = (B + 1) >> 1;
    int p = blockIdx.x * HNT + lane;
    if (p >= pairs) p = pairs - 1;        // clamp: duplicate work, benign
    const int e0 = p * 2;
    const int e1 = (e0 + 1 < B) ? e0 + 1 : B - 1;
    const int m0 = half * 4;

    const u64 c505 = pack2(0.505f, 0.505f);
    const u64 c495 = pack2(0.495f, 0.495f);

    const float2 ssA = reinterpret_cast<const float2*>(SS)[e0];
    const float2 ssB = reinterpret_cast<const float2*>(SS)[e1];

    float Ksum[2] = {0.f, 0.f};
    float Bsum[2] = {0.f, 0.f};

#pragma unroll 1
    for (int mi = 0; mi < 4; mi++) {
        const int m = m0 + mi;
        const float* mb = sm + m * PM;
        const float Msv = mb[OFF_PAR + 4];

        float a0 = fminf(fmaxf(__ldg(&AL[(size_t)e0 * 8 + m]), 0.0f), 1.0f);
        float a1 = fminf(fmaxf(__ldg(&AL[(size_t)e1 * 8 + m]), 0.0f), 1.0f);
        float l0v = ssA.x * Msv, l1v = ssB.x * Msv;
        u64 xl[2] = { pack2(l0v, l0v),                 pack2(l1v, l1v) };
        u64 xd[2] = { pack2(ssA.y * Msv, ssA.y * Msv), pack2(ssB.y * Msv, ssB.y * Msv) };
        u64 xa[2] = { pack2(a0, a0),                   pack2(a1, a1) };

        // ---- layer 1 (3 -> 32): hp[q][p] = {h_2p, h_2p+1} ----
        u64 hp[2][16];
        {
            const u64* b1p = reinterpret_cast<const u64*>(mb + OFF_B1P);
            const u64* w0r = reinterpret_cast<const u64*>(mb + OFF_W1T);
            const u64* w1r = reinterpret_cast<const u64*>(mb + OFF_W1T + 32);
            const u64* w2r = reinterpret_cast<const u64*>(mb + OFF_W1T + 64);
#pragma unroll
            for (int pp = 0; pp < 16; pp++) {
                u64 w0 = w0r[pp], w1 = w1r[pp], w2 = w2r[pp], bb = b1p[pp];
                u64 acc0 = fma2(xl[0], w0, bb);
                u64 acc1 = fma2(xl[1], w0, bb);
                acc0 = fma2(xd[0], w1, acc0);
                acc1 = fma2(xd[1], w1, acc1);
                acc0 = fma2(xa[0], w2, acc0);
                acc1 = fma2(xa[1], w2, acc1);
                hp[0][pp] = leaky2(acc0, c505, c495);
                hp[1][pp] = leaky2(acc1, c505, c495);
            }
        }

        // ---- layers 2 & 3 (32 -> 32), parity-split accumulation ----
#pragma unroll 1
        for (int L = 0; L < 2; L++) {
            const float* W  = mb + (L ? OFF_W3 : OFF_W2);
            const u64*  BZ  = reinterpret_cast<const u64*>(mb + (L ? OFF_B3Z : OFF_B2Z));
            u64 hn[2][16];
#pragma unroll
            for (int og = 0; og < 8; og++) {
                const float* wr = W + og * 128;
                u64 acc[8];
#pragma unroll
                for (int r = 0; r < 4; r++) { u64 b = BZ[og * 4 + r]; acc[r] = b; acc[4 + r] = b; }
#pragma unroll
                for (int ip = 0; ip < 16; ip += 2) {
                    ulonglong2 w0 = *reinterpret_cast<const ulonglong2*>(wr +  0 + ip * 2);
                    ulonglong2 w1 = *reinterpret_cast<const ulonglong2*>(wr + 32 + ip * 2);
                    ulonglong2 w2 = *reinterpret_cast<const ulonglong2*>(wr + 64 + ip * 2);
                    ulonglong2 w3 = *reinterpret_cast<const ulonglong2*>(wr + 96 + ip * 2);
                    acc[0] = fma2(hp[0][ip], w0.x, acc[0]);
                    acc[1] = fma2(hp[0][ip], w1.x, acc[1]);
                    acc[2] = fma2(hp[0][ip], w2.x, acc[2]);
                    acc[3] = fma2(hp[0][ip], w3.x, acc[3]);
                    acc[4] = fma2(hp[1][ip], w0.x, acc[4]);
                    acc[5] = fma2(hp[1][ip], w1.x, acc[5]);
                    acc[6] = fma2(hp[1][ip], w2.x, acc[6]);
                    acc[7] = fma2(hp[1][ip], w3.x, acc[7]);
                    acc[0] = fma2(hp[0][ip+1], w0.y, acc[0]);
                    acc[1] = fma2(hp[0][ip+1], w1.y, acc[1]);
                    acc[2] = fma2(hp[0][ip+1], w2.y, acc[2]);
                    acc[3] = fma2(hp[0][ip+1], w3.y, acc[3]);
                    acc[4] = fma2(hp[1][ip+1], w0.y, acc[4]);
                    acc[5] = fma2(hp[1][ip+1], w1.y, acc[5]);
                    acc[6] = fma2(hp[1][ip+1], w2.y, acc[6]);
                    acc[7] = fma2(hp[1][ip+1], w3.y, acc[7]);
                }
#pragma unroll
                for (int q = 0; q < 2; q++) {
                    float x0, y0, x1, y1;
                    unpack2(acc[q*4+0], x0, y0);
                    unpack2(acc[q*4+1], x1, y1);
                    hn[q][og*2]   = pack2(leakys(x0 + y0), leakys(x1 + y1));
                    unpack2(acc[q*4+2], x0, y0);
                    unpack2(acc[q*4+3], x1, y1);
                    hn[q][og*2+1] = pack2(leakys(x0 + y0), leakys(x1 + y1));
                }
            }
#pragma unroll
            for (int pp = 0; pp < 16; pp++) { hp[0][pp] = hn[0][pp]; hp[1][pp] = hn[1][pp]; }
        }

        // ---- layer 4 (32 -> 1) + tanh ----
        const u64* w4p = reinterpret_cast<const u64*>(mb + OFF_W4);
        const float b4v = mb[OFF_B4];
        float nn[2];
#pragma unroll
        for (int q = 0; q < 2; q++) {
            u64 sA = 0ull, sB = 0ull;
#pragma unroll
            for (int ip = 0; ip < 16; ip += 2) {
                sA = fma2(hp[q][ip],   w4p[ip],   sA);
                sB = fma2(hp[q][ip+1], w4p[ip+1], sB);
            }
            u64 s = add2(sA, sB);
            float lo, hi; unpack2(s, lo, hi);
            nn[q] = NNR * tanh_ap(lo + hi + b4v);
        }

        // ---- muscle epilogue (par scalars loaded late, after MLP) ----
        const float K0v = mb[OFF_PAR + 0], K1v = mb[OFF_PAR + 1];
        const float L0v = mb[OFF_PAR + 2], L1v = mb[OFF_PAR + 3];
        const float Ms2v = mb[OFF_PAR + 5], K1L1v = mb[OFF_PAR + 6];
        {
            float K = fmaf(a0, K1v, K0v);
            Ksum[0] = fmaf(K, Ms2v, Ksum[0]);
            float tL = fmaf(a0, L1v, L0v) - fabsf(l0v);
            float BF = fmaf(a0 * a0 * nn[0], K1L1v, K * tL);
            Bsum[0] = fmaf(BF, Msv, Bsum[0]);
        }
        {
            float K = fmaf(a1, K1v, K0v);
            Ksum[1] = fmaf(K, Ms2v, Ksum[1]);
            float tL = fmaf(a1, L1v, L0v) - fabsf(l1v);
            float BF = fmaf(a1 * a1 * nn[1], K1L1v, K * tL);
            Bsum[1] = fmaf(BF, Msv, Bsum[1]);
        }
    }

    // ---- combine halves through smem ----
    float4* red = reinterpret_cast<float4*>(sm + OFF_RED);
    if (half == 1)
        red[lane] = make_float4(Ksum[0], Bsum[0], Ksum[1], Bsum[1]);
    __syncthreads();

    if (half == 0) {
        float4 r = red[lane];
        Ksum[0] += r.x; Bsum[0] += r.y;
        Ksum[1] += r.z; Bsum[1] += r.w;

        const float Iv = __ldg(Ip), Bv = __ldg(Bvp), Kv = __ldg(Kvp);
        const float invI = 1.0f / Iv;

        float2* seg2 = reinterpret_cast<float2*>(out + B);
        float o0, o1;
        finalize(Ksum[0], Bsum[0], ssA.x, ssA.y, Iv, invI, Bv, Kv, o0, o1);
        out[e0]  = o0;
        seg2[e0] = make_float2(o0, o1);
        finalize(Ksum[1], Bsum[1], ssB.x, ssB.y, Iv, invI, Bv, Kv, o0, o1);
        out[e1]  = o0;
        seg2[e1] = make_float2(o0, o1);
    }
}

extern "C" void kernel_launch(void* const* d_in, const int* in_sizes, int n_in,
                              void* d_out, int out_size) {
    const float* SS  = (const float*)d_in[0];
    const float* AL  = (const float*)d_in[1];
    const float* K0  = (const float*)d_in[2];
    const float* K1  = (const float*)d_in[3];
    const float* L0  = (const float*)d_in[4];
    const float* L1  = (const float*)d_in[5];
    const float* Ms  = (const float*)d_in[6];
    const float* Ip  = (const float*)d_in[7];
    const float* Bv  = (const float*)d_in[8];
    const float* Kv  = (const float*)d_in[9];
    const float* W1  = (const float*)d_in[10];
    const float* b1  = (const float*)d_in[11];
    const float* W2  = (const float*)d_in[12];
    const float* b2  = (const float*)d_in[13];
    const float* W3  = (const float*)d_in[14];
    const float* b3  = (const float*)d_in[15];
    const float* W4  = (const float*)d_in[16];
    const float* b4  = (const float*)d_in[17];
    float* out = (float*)d_out;

    const int B = in_sizes[0] / 2;
    const int pairs = (B + 1) / 2;
    const int grid = (pairs + HNT - 1) / HNT;

    cudaFuncSetAttribute(joint_kernel, cudaFuncAttributeMaxDynamicSharedMemorySize, SMEM_BYTES);
    joint_kernel<<<grid, NT, SMEM_BYTES>>>(SS, AL, K0, K1, L0, L1, Ms, Ip, Bv, Kv,
                                           W1, b1, W2, b2, W3, b3, W4, b4, out, B);
}

// round 5
// speedup vs baseline: 1.0287x; 1.0287x over previous
#include <cuda_runtime.h>
#include <cstdint>
#include <cmath>

typedef unsigned long long u64;

#define NT 448                  // 14 warps per CTA, 1 CTA/SM, grid=147
#define HNT 224                 // pair slots per CTA (two muscle-halves)
#define PM 2344                 // floats per muscle block in smem
#define OFF_W1T 0               // 3*32 transposed [i][o]
#define OFF_B1P 96              // 32
#define OFF_W2  128             // 32*32 NATIVE [o][i]
#define OFF_B2Z 1152            // 64  ({b_o, 0} interleaved)
#define OFF_W3  1216            // 32*32 NATIVE [o][i]
#define OFF_B3Z 2240            // 64
#define OFF_W4  2304            // 32 native [i]
#define OFF_B4  2336            // 1
#define OFF_PAR 2337            // 7: K0,K1,L0,L1,Ms,Ms2,K1L1
#define SCR_F   (8*PM)          // per-thread activation scratch: 32 u64 * NT
#define OFF_RED (SCR_F + 32*NT*2)   // reduction buffer: HNT float4
#define SMEM_BYTES ((OFF_RED + HNT*4)*4)
#define DTC 0.0166667f
#define NNR 0.3f

// ---------- packed f32x2 helpers ----------
__device__ __forceinline__ u64 fma2(u64 a, u64 b, u64 c) {
    u64 d; asm("fma.rn.f32x2 %0, %1, %2, %3;" : "=l"(d) : "l"(a), "l"(b), "l"(c)); return d;
}
__device__ __forceinline__ u64 add2(u64 a, u64 b) {
    u64 d; asm("add.rn.f32x2 %0, %1, %2;" : "=l"(d) : "l"(a), "l"(b)); return d;
}
__device__ __forceinline__ u64 mul2(u64 a, u64 b) {
    u64 d; asm("mul.rn.f32x2 %0, %1, %2;" : "=l"(d) : "l"(a), "l"(b)); return d;
}
__device__ __forceinline__ u64 pack2(float lo, float hi) {
    u64 r; asm("mov.b64 %0, {%1, %2};" : "=l"(r) : "r"(__float_as_uint(lo)), "r"(__float_as_uint(hi))); return r;
}
__device__ __forceinline__ void unpack2(u64 v, float& lo, float& hi) {
    unsigned a, b; asm("mov.b64 {%0, %1}, %2;" : "=r"(a), "=r"(b) : "l"(v));
    lo = __uint_as_float(a); hi = __uint_as_float(b);
}
__device__ __forceinline__ float tanh_ap(float x) {
    float y; asm("tanh.approx.f32 %0, %1;" : "=f"(y) : "f"(x)); return y;
}
__device__ __forceinline__ u64 leaky2(u64 x, u64 c505, u64 c495) {
    u64 ax = x & 0x7FFFFFFF7FFFFFFFull;
    return fma2(x, c505, mul2(ax, c495));
}
__device__ __forceinline__ float leakys(float x) {
    return fmaf(0.505f, x, 0.495f * fabsf(x));
}

// closed-form 2x2 expm + phi1 solve (validated: rel_err 5.7e-7)
__device__ __forceinline__ void finalize(float Ks, float Bs, float s0, float s1,
                                         float Iv, float invI, float Bv, float Kv,
                                         float& o0, float& o1) {
    float A10 = -(Ks + Kv) * invI;
    float Dd  = 2.0f * sqrtf(fmaxf(Ks * Iv, 0.0f));
    float A11 = -(Dd + Bv) * invI;
    float B10 = Bs * invI;
    float a10 = A10 * DTC, a11 = A11 * DTC;
    float s = 0.5f * a11;
    float q = fmaf(s, s, DTC * a10);
    float c, kf;
    if (q >= 0.0f) {
        float w = sqrtf(q);
        c = coshf(w);
        kf = (w > 1e-4f) ? sinhf(w) / w : 1.0f + q * (1.0f / 6.0f);
    } else {
        float w = sqrtf(-q);
        c = __cosf(w);
        kf = (w > 1e-4f) ? __sinf(w) / w : 1.0f + q * (1.0f / 6.0f);
    }
    float es = __expf(s);
    float g  = es * fmaf(-s, kf, c);
    float kk = es * kf;
    float Ad01 = kk * DTC;
    float Ad10 = kk * a10;
    float Ad11 = g + kk * a11;
    float v  = DTC * B10;
    float y1 = kk * v;
    float r1 = (Ad11 - 1.0f) * v;
    float y0 = (r1 - a11 * y1) / a10;
    o0 = fmaf(g,    s0, fmaf(Ad01, s1, y0));
    o1 = fmaf(Ad10, s0, fmaf(Ad11, s1, y1));
}

__global__ __launch_bounds__(NT, 1)
void joint_kernel(const float* __restrict__ SS,  const float* __restrict__ AL,
                  const float* __restrict__ K0,  const float* __restrict__ K1,
                  const float* __restrict__ L0,  const float* __restrict__ L1,
                  const float* __restrict__ Ms,  const float* __restrict__ Ip,
                  const float* __restrict__ Bvp, const float* __restrict__ Kvp,
                  const float* __restrict__ W1,  const float* __restrict__ b1,
                  const float* __restrict__ W2,  const float* __restrict__ b2,
                  const float* __restrict__ W3,  const float* __restrict__ b3,
                  const float* __restrict__ W4,  const float* __restrict__ b4,
                  float* __restrict__ out, int B) {
    extern __shared__ float sm[];
    const int tid = threadIdx.x;

    // ---- smem tables ----
    for (int t = tid; t < 768; t += NT) {            // W1[m][o][i] -> [m][i][o]
        int m = t / 96, r = t - m * 96, o = r / 3, i = r - o * 3;
        sm[m * PM + OFF_W1T + i * 32 + o] = W1[t];
    }
    for (int t = tid; t < 256; t += NT) {            // b1 native
        int m = t >> 5, o = t & 31;
        sm[m * PM + OFF_B1P + o] = b1[t];
    }
    {                                                // W2, W3 native copies (float4)
        const float4* s2 = reinterpret_cast<const float4*>(W2);
        const float4* s3 = reinterpret_cast<const float4*>(W3);
        for (int t = tid; t < 2048; t += NT) {
            int m = t >> 8, r = t & 255;
            *reinterpret_cast<float4*>(&sm[m * PM + OFF_W2 + r * 4]) = s2[t];
            *reinterpret_cast<float4*>(&sm[m * PM + OFF_W3 + r * 4]) = s3[t];
        }
    }
    for (int t = tid; t < 512; t += NT) {            // b2, b3 as {b, 0}
        int m = t >> 6, r = t & 63;
        float v2 = (r & 1) ? 0.0f : b2[m * 32 + (r >> 1)];
        float v3 = (r & 1) ? 0.0f : b3[m * 32 + (r >> 1)];
        sm[m * PM + OFF_B2Z + r] = v2;
        sm[m * PM + OFF_B3Z + r] = v3;
    }
    for (int t = tid; t < 256; t += NT) {            // W4 native
        int m = t >> 5, i = t & 31;
        sm[m * PM + OFF_W4 + i] = W4[t];
    }
    if (tid < 8) {
        int m = tid;
        sm[m * PM + OFF_B4] = b4[m];
        float k0 = K0[m], k1 = K1[m], l0 = L0[m], l1 = L1[m], ms = Ms[m];
        float* p = sm + m * PM + OFF_PAR;
        p[0] = k0; p[1] = k1; p[2] = l0; p[3] = l1;
        p[4] = ms; p[5] = ms * ms; p[6] = k1 * l1;
    }
    __syncthreads();

    // thread -> (pair, muscle half)
    const int lane  = tid % HNT;
    const int half  = tid / HNT;          // 0: muscles 0-3, 1: muscles 4-7
    const int pairs = (B + 1) >> 1;
    int p = blockIdx.x * HNT + lane;
    if (p >= pairs) p = pairs - 1;        // clamp: duplicate work, benign
    const int e0 = p * 2;
    const int e1 = (e0 + 1 < B) ? e0 + 1 : B - 1;
    const int m0 = half * 4;

    const u64 c505 = pack2(0.505f, 0.505f);
    const u64 c495 = pack2(0.495f, 0.495f);

    const float2 ssA = reinterpret_cast<const float2*>(SS)[e0];
    const float2 ssB = reinterpret_cast<const float2*>(SS)[e1];

    u64* scr = reinterpret_cast<u64*>(sm + SCR_F) + tid;   // private slots, stride NT

    float Ksum[2] = {0.f, 0.f};
    float Bsum[2] = {0.f, 0.f};

#pragma unroll 1
    for (int mi = 0; mi < 4; mi++) {
        const int m = m0 + mi;
        const float* mb = sm + m * PM;
        const float Msv = mb[OFF_PAR + 4];

        float a0 = fminf(fmaxf(__ldg(&AL[(size_t)e0 * 8 + m]), 0.0f), 1.0f);
        float a1 = fminf(fmaxf(__ldg(&AL[(size_t)e1 * 8 + m]), 0.0f), 1.0f);
        float l0v = ssA.x * Msv, l1v = ssB.x * Msv;

        // ---- layer 1 (3 -> 32): hp[q][p] = {h_2p, h_2p+1} ----
        u64 hp[2][16];
        {
            u64 xl[2] = { pack2(l0v, l0v),                 pack2(l1v, l1v) };
            u64 xd[2] = { pack2(ssA.y * Msv, ssA.y * Msv), pack2(ssB.y * Msv, ssB.y * Msv) };
            u64 xa[2] = { pack2(a0, a0),                   pack2(a1, a1) };
            const u64* b1p = reinterpret_cast<const u64*>(mb + OFF_B1P);
            const u64* w0r = reinterpret_cast<const u64*>(mb + OFF_W1T);
            const u64* w1r = reinterpret_cast<const u64*>(mb + OFF_W1T + 32);
            const u64* w2r = reinterpret_cast<const u64*>(mb + OFF_W1T + 64);
#pragma unroll
            for (int pp = 0; pp < 16; pp++) {
                u64 w0 = w0r[pp], w1 = w1r[pp], w2 = w2r[pp], bb = b1p[pp];
                u64 acc0 = fma2(xl[0], w0, bb);
                u64 acc1 = fma2(xl[1], w0, bb);
                acc0 = fma2(xd[0], w1, acc0);
                acc1 = fma2(xd[1], w1, acc1);
                acc0 = fma2(xa[0], w2, acc0);
                acc1 = fma2(xa[1], w2, acc1);
                hp[0][pp] = leaky2(acc0, c505, c495);
                hp[1][pp] = leaky2(acc1, c505, c495);
            }
        }

        // ---- layers 2 & 3 (32 -> 32): outputs staged through private smem scratch ----
#pragma unroll 1
        for (int L = 0; L < 2; L++) {
            const float* W  = mb + (L ? OFF_W3 : OFF_W2);
            const u64*  BZ  = reinterpret_cast<const u64*>(mb + (L ? OFF_B3Z : OFF_B2Z));
#pragma unroll
            for (int og = 0; og < 8; og++) {
                const float* wr = W + og * 128;
                u64 acc[8];
#pragma unroll
                for (int r = 0; r < 4; r++) { u64 b = BZ[og * 4 + r]; acc[r] = b; acc[4 + r] = b; }
#pragma unroll
                for (int ip = 0; ip < 16; ip += 2) {
                    ulonglong2 w0 = *reinterpret_cast<const ulonglong2*>(wr +  0 + ip * 2);
                    ulonglong2 w1 = *reinterpret_cast<const ulonglong2*>(wr + 32 + ip * 2);
                    ulonglong2 w2 = *reinterpret_cast<const ulonglong2*>(wr + 64 + ip * 2);
                    ulonglong2 w3 = *reinterpret_cast<const ulonglong2*>(wr + 96 + ip * 2);
                    acc[0] = fma2(hp[0][ip], w0.x, acc[0]);
                    acc[1] = fma2(hp[0][ip], w1.x, acc[1]);
                    acc[2] = fma2(hp[0][ip], w2.x, acc[2]);
                    acc[3] = fma2(hp[0][ip], w3.x, acc[3]);
                    acc[4] = fma2(hp[1][ip], w0.x, acc[4]);
                    acc[5] = fma2(hp[1][ip], w1.x, acc[5]);
                    acc[6] = fma2(hp[1][ip], w2.x, acc[6]);
                    acc[7] = fma2(hp[1][ip], w3.x, acc[7]);
                    acc[0] = fma2(hp[0][ip+1], w0.y, acc[0]);
                    acc[1] = fma2(hp[0][ip+1], w1.y, acc[1]);
                    acc[2] = fma2(hp[0][ip+1], w2.y, acc[2]);
                    acc[3] = fma2(hp[0][ip+1], w3.y, acc[3]);
                    acc[4] = fma2(hp[1][ip+1], w0.y, acc[4]);
                    acc[5] = fma2(hp[1][ip+1], w1.y, acc[5]);
                    acc[6] = fma2(hp[1][ip+1], w2.y, acc[6]);
                    acc[7] = fma2(hp[1][ip+1], w3.y, acc[7]);
                }
#pragma unroll
                for (int q = 0; q < 2; q++) {
                    float x0, y0, x1, y1;
                    unpack2(acc[q*4+0], x0, y0);
                    unpack2(acc[q*4+1], x1, y1);
                    scr[(q*16 + og*2) * NT]     = pack2(leakys(x0 + y0), leakys(x1 + y1));
                    unpack2(acc[q*4+2], x0, y0);
                    unpack2(acc[q*4+3], x1, y1);
                    scr[(q*16 + og*2 + 1) * NT] = pack2(leakys(x0 + y0), leakys(x1 + y1));
                }
            }
            // reload activations (private slots; no barrier needed)
#pragma unroll
            for (int pp = 0; pp < 16; pp++) {
                hp[0][pp] = scr[pp * NT];
                hp[1][pp] = scr[(16 + pp) * NT];
            }
        }

        // ---- layer 4 (32 -> 1) + tanh ----
        const u64* w4p = reinterpret_cast<const u64*>(mb + OFF_W4);
        const float b4v = mb[OFF_B4];
        float nn[2];
#pragma unroll
        for (int q = 0; q < 2; q++) {
            u64 sA = 0ull, sB = 0ull;
#pragma unroll
            for (int ip = 0; ip < 16; ip += 2) {
                sA = fma2(hp[q][ip],   w4p[ip],   sA);
                sB = fma2(hp[q][ip+1], w4p[ip+1], sB);
            }
            u64 s = add2(sA, sB);
            float lo, hi; unpack2(s, lo, hi);
            nn[q] = NNR * tanh_ap(lo + hi + b4v);
        }

        // ---- muscle epilogue ----
        const float K0v = mb[OFF_PAR + 0], K1v = mb[OFF_PAR + 1];
        const float L0v = mb[OFF_PAR + 2], L1v = mb[OFF_PAR + 3];
        const float Ms2v = mb[OFF_PAR + 5], K1L1v = mb[OFF_PAR + 6];
        {
            float K = fmaf(a0, K1v, K0v);
            Ksum[0] = fmaf(K, Ms2v, Ksum[0]);
            float tL = fmaf(a0, L1v, L0v) - fabsf(l0v);
            float BF = fmaf(a0 * a0 * nn[0], K1L1v, K * tL);
            Bsum[0] = fmaf(BF, Msv, Bsum[0]);
        }
        {
            float K = fmaf(a1, K1v, K0v);
            Ksum[1] = fmaf(K, Ms2v, Ksum[1]);
            float tL = fmaf(a1, L1v, L0v) - fabsf(l1v);
            float BF = fmaf(a1 * a1 * nn[1], K1L1v, K * tL);
            Bsum[1] = fmaf(BF, Msv, Bsum[1]);
        }
    }

    // ---- combine halves through smem ----
    float4* red = reinterpret_cast<float4*>(sm + OFF_RED);
    __syncthreads();                       // scratch reuse safety + reduction ordering
    if (half == 1)
        red[lane] = make_float4(Ksum[0], Bsum[0], Ksum[1], Bsum[1]);
    __syncthreads();

    if (half == 0) {
        float4 r = red[lane];
        Ksum[0] += r.x; Bsum[0] += r.y;
        Ksum[1] += r.z; Bsum[1] += r.w;

        const float Iv = __ldg(Ip), Bv = __ldg(Bvp), Kv = __ldg(Kvp);
        const float invI = 1.0f / Iv;

        float2* seg2 = reinterpret_cast<float2*>(out + B);
        float o0, o1;
        finalize(Ksum[0], Bsum[0], ssA.x, ssA.y, Iv, invI, Bv, Kv, o0, o1);
        out[e0]  = o0;
        seg2[e0] = make_float2(o0, o1);
        finalize(Ksum[1], Bsum[1], ssB.x, ssB.y, Iv, invI, Bv, Kv, o0, o1);
        out[e1]  = o0;
        seg2[e1] = make_float2(o0, o1);
    }
}

extern "C" void kernel_launch(void* const* d_in, const int* in_sizes, int n_in,
                              void* d_out, int out_size) {
    const float* SS  = (const float*)d_in[0];
    const float* AL  = (const float*)d_in[1];
    const float* K0  = (const float*)d_in[2];
    const float* K1  = (const float*)d_in[3];
    const float* L0  = (const float*)d_in[4];
    const float* L1  = (const float*)d_in[5];
    const float* Ms  = (const float*)d_in[6];
    const float* Ip  = (const float*)d_in[7];
    const float* Bv  = (const float*)d_in[8];
    const float* Kv  = (const float*)d_in[9];
    const float* W1  = (const float*)d_in[10];
    const float* b1  = (const float*)d_in[11];
    const float* W2  = (const float*)d_in[12];
    const float* b2  = (const float*)d_in[13];
    const float* W3  = (const float*)d_in[14];
    const float* b3  = (const float*)d_in[15];
    const float* W4  = (const float*)d_in[16];
    const float* b4  = (const float*)d_in[17];
    float* out = (float*)d_out;

    const int B = in_sizes[0] / 2;
    const int pairs = (B + 1) / 2;
    const int grid = (pairs + HNT - 1) / HNT;

    cudaFuncSetAttribute(joint_kernel, cudaFuncAttributeMaxDynamicSharedMemorySize, SMEM_BYTES);
    joint_kernel<<<grid, NT, SMEM_BYTES>>>(SS, AL, K0, K1, L0, L1, Ms, Ip, Bv, Kv,
                                           W1, b1, W2, b2, W3, b3, W4, b4, out, B);
}